// round 17
// baseline (speedup 1.0000x reference)
#include <cuda_runtime.h>
#include <math.h>

// Problem constants
#define LQ 128     // sequence length
#define TT 127     // T = L-1 output rows
#define EE 256     // embedding dim
#define HH 512     // hidden
#define G4 2048    // 4*H gates
#define VV 32000   // vocab
#define KH2 1024   // 2*H

#define NB 128     // persistent scan blocks (one per SM, all co-resident)
#define NT 256     // threads per scan block
#define TP 192     // padded t-columns in k-major global h

typedef unsigned long long ull;

// ---------------- device scratch (no allocs allowed) ----------------
__device__ float g_gxf[LQ][G4];        // emb @ W_ih_f^T + b_f
__device__ float g_gxb[LQ][G4];        // emb @ W_ih_b^T + b_b
__device__ float g_hf_all[TT][HH];     // forward hidden states
__device__ float g_hb_final[TT][HH];   // final backward hidden per row t
__device__ float g_hbT[2][HH][TP];     // double-buffered backward h, K-MAJOR
__device__ float g_hfwd[2][HH];        // double-buffered forward h
__device__ unsigned g_cnt;             // grid barrier arrive counter
__device__ unsigned g_gen;             // grid barrier generation

__device__ __forceinline__ float sigmoidf_(float x) {
    return 1.f / (1.f + expf(-x));
}

__device__ __forceinline__ ull fma2_(ull a, ull b, ull c) {
    ull d;
    asm("fma.rn.f32x2 %0, %1, %2, %3;" : "=l"(d) : "l"(a), "l"(b), "l"(c));
    return d;
}
__device__ __forceinline__ float lo_(ull p) {
    return __uint_as_float((unsigned)(p & 0xffffffffull));
}
__device__ __forceinline__ float hi_(ull p) {
    return __uint_as_float((unsigned)(p >> 32));
}

__device__ __forceinline__ void cp_async16_(void* smem, const void* gmem) {
    unsigned saddr = (unsigned)__cvta_generic_to_shared(smem);
    asm volatile("cp.async.cg.shared.global [%0], [%1], 16;\n"
                 :: "r"(saddr), "l"(gmem) : "memory");
}
#define CP_COMMIT() asm volatile("cp.async.commit_group;\n" ::: "memory")
#define CP_WAIT0()  asm volatile("cp.async.wait_group 0;\n" ::: "memory")
#define CP_WAIT1()  asm volatile("cp.async.wait_group 1;\n" ::: "memory")

// ---------------- init: zero state + barrier vars ----------------
__global__ void init_kernel() {
    int idx = blockIdx.x * blockDim.x + threadIdx.x;
    int stride = gridDim.x * blockDim.x;
    float* h0 = &g_hbT[0][0][0];
    for (int i = idx; i < HH * TP; i += stride) h0[i] = 0.f;
    if (idx < HH) g_hfwd[0][idx] = 0.f;
    if (idx == 0) { g_cnt = 0u; g_gen = 0u; }
}

// ---------------- gather + input GEMM (both directions) ----------------
__global__ void input_gemm_kernel(const int* __restrict__ x,
                                  const float* __restrict__ emb,
                                  const float* __restrict__ Wf,
                                  const float* __restrict__ bif,
                                  const float* __restrict__ bhf,
                                  const float* __restrict__ Wb,
                                  const float* __restrict__ bib,
                                  const float* __restrict__ bhb) {
    __shared__ float sW[16][EE];
    bool isB = (blockIdx.x >= 128);
    int j0 = (isB ? (blockIdx.x - 128) : blockIdx.x) * 16;
    const float* W  = isB ? Wb  : Wf;
    const float* bi = isB ? bib : bif;
    const float* bh = isB ? bhb : bhf;
    int tid = threadIdx.x;  // 128 threads

    for (int u = tid; u < 16 * EE; u += 128)
        sW[u >> 8][u & 255] = W[(j0 + (u >> 8)) * EE + (u & 255)];
    __syncthreads();

    int t = tid;
    int tok = x[t];
    const float* er = emb + (long)tok * EE;
    float acc[16];
#pragma unroll
    for (int r = 0; r < 16; r++) acc[r] = 0.f;

    for (int e = 0; e < EE; e += 4) {
        float4 e4 = *(const float4*)(er + e);
#pragma unroll
        for (int r = 0; r < 16; r++) {
            float4 w4 = *(const float4*)&sW[r][e];
            acc[r] += e4.x * w4.x + e4.y * w4.y + e4.z * w4.z + e4.w * w4.w;
        }
    }
    float* gx = isB ? &g_gxb[t][0] : &g_gxf[t][0];
#pragma unroll
    for (int r = 0; r < 16; r++) {
        int j = j0 + r;
        gx[j] = acc[r] + bi[j] + bh[j];
    }
}

// ---------------- persistent LSTM scan kernel ----------------
// 128 blocks, each owns 4 hidden dims (16 gate rows per direction).
// W_b lives in smem PRE-DUPLICATED (sWb2[k][2r],[2r+1] both = W[r][k]) so one
// LDS.128 yields two packed f32x2 w-operands -> no MOV duplication.
// h tile: 32 t cols, k-major, DOUBLE-BUFFERED; tile i+1 staged via cp.async
// before GEMM(i) runs -> staging fully hidden behind compute.
// Warp = kq (0..7, 64 k each); lane: g = lane&3 (gate), tq = lane>>2 (4 t's).
// Per k: 2x LDS.128 (w dup pairs) + 1x LDS.128 (4 t) + 8 FFMA2 (4q x 2 t-pairs).
extern __shared__ float dyn_smem[];

__global__ void __launch_bounds__(NT, 1)
scan_kernel(const float* __restrict__ Whf, const float* __restrict__ Whb) {
    float* sWb2 = dyn_smem;              // [512][32] dup'd W_b   64 KB
    float* shT  = sWb2 + 512 * 32;       // [2][512][32] h tiles 128 KB
    __shared__ float sgp[8][4][32][4];   // partials [kq][gate][tc][q] 16 KB
    __shared__ float scb[TT][4];         // backward c, block's 4 dims
    __shared__ float shf[HH];            // forward h
    __shared__ float sgf[16];            // forward gate staging
    __shared__ float scf[4];             // forward c

    int tid = threadIdx.x;
    int k0 = blockIdx.x * 4;

    // stage W_b once, duplicated: r = gate*4 + q -> global j = gate*HH + k0 + q
    for (int u = tid; u < 512 * 16; u += NT) {
        int k = u >> 4, r = u & 15;
        int j = (r >> 2) * HH + k0 + (r & 3);
        float w = Whb[(long)j * HH + k];
        sWb2[k * 32 + 2 * r]     = w;
        sWb2[k * 32 + 2 * r + 1] = w;
    }
    for (int u = tid; u < TT; u += NT) {
        scb[u][0] = 0.f; scb[u][1] = 0.f; scb[u][2] = 0.f; scb[u][3] = 0.f;
    }
    if (tid < 4) scf[tid] = 0.f;
    __syncthreads();

    int lane = tid & 31;
    int warp = tid >> 5;     // 8 warps = 8 k-slices of 64
    int g    = lane & 3;     // gate
    int tq   = lane >> 2;    // 0..7 -> t cols 4*tq .. 4*tq+3

    for (int s = 0; s < TT; s++) {
        int p = s & 1, p2 = p ^ 1;
        int tb0 = s & ~3;
        int nt = (TT - tb0 + 31) >> 5;   // number of 32t tiles

        // ---- group 0: stage forward h; group 1: stage tile 0 ----
        if (tid < 128) cp_async16_(shf + 4 * tid, &g_hfwd[p][4 * tid]);
        CP_COMMIT();
        for (int u = tid; u < 4096; u += NT) {
            int k = u >> 3, seg = u & 7;
            cp_async16_(shT + k * 32 + seg * 4, &g_hbT[p][k][tb0 + seg * 4]);
        }
        CP_COMMIT();

        // ======== forward chain (16 rows), W_f streamed from L2 ========
        CP_WAIT1();          // shf ready (tile 0 may still be in flight)
        __syncthreads();
        {
            int r0 = 2 * warp;
            int ja = (r0 >> 2) * HH + k0 + (r0 & 3);
            int jb = ((r0 + 1) >> 2) * HH + k0 + ((r0 + 1) & 3);
            const float* w0 = Whf + (long)ja * HH;
            const float* w1 = Whf + (long)jb * HH;
            float a0 = 0.f, a1 = 0.f;
#pragma unroll
            for (int m = 0; m < 16; m++) {
                float h = shf[lane + 32 * m];
                a0 += w0[lane + 32 * m] * h;
                a1 += w1[lane + 32 * m] * h;
            }
#pragma unroll
            for (int off = 16; off >= 1; off >>= 1) {
                a0 += __shfl_xor_sync(0xffffffffu, a0, off);
                a1 += __shfl_xor_sync(0xffffffffu, a1, off);
            }
            if (lane == 0) { sgf[r0] = a0; sgf[r0 + 1] = a1; }
        }
        __syncthreads();
        if (tid < 4) {
            int q = tid, jb = k0 + q;
            float gi = sgf[0 * 4 + q] + g_gxf[s][jb];
            float gf = sgf[1 * 4 + q] + g_gxf[s][HH + jb];
            float gg = sgf[2 * 4 + q] + g_gxf[s][2 * HH + jb];
            float go = sgf[3 * 4 + q] + g_gxf[s][3 * HH + jb];
            float c  = scf[q];
            float cn = sigmoidf_(gf) * c + sigmoidf_(gi) * tanhf(gg);
            float hn = sigmoidf_(go) * tanhf(cn);
            scf[q] = cn;
            g_hfwd[p2][jb]  = hn;
            g_hf_all[s][jb] = hn;
        }

        // ======== backward prefix LSTMs: pipelined 32t tiles ========
        for (int i = 0; i < nt; i++) {
            int tb = tb0 + 32 * i;
            // stage-ahead: tile i+1 into the other buffer
            if (i + 1 < nt) {
                float* dst = shT + ((i + 1) & 1) * 512 * 32;
                int tn = tb + 32;
                for (int u = tid; u < 4096; u += NT) {
                    int k = u >> 3, seg = u & 7;
                    cp_async16_(dst + k * 32 + seg * 4,
                                &g_hbT[p][k][tn + seg * 4]);
                }
                CP_COMMIT();
                CP_WAIT1();     // tile i ready, tile i+1 in flight
            } else {
                CP_WAIT0();     // tile i ready
            }
            __syncthreads();

            const float* shb = shT + (i & 1) * 512 * 32;
            // micro-tile: gate g's 4 q x 4 t over this warp's 64-k slice
            ull a00 = 0, a01 = 0, a10 = 0, a11 = 0;
            ull a20 = 0, a21 = 0, a30 = 0, a31 = 0;
            const float* wp = sWb2 + (warp * 64) * 32 + 8 * g;
            const float* hp = shb + (warp * 64) * 32 + 4 * tq;
#pragma unroll 8
            for (int k = 0; k < 64; k++) {
                float4 wA = *(const float4*)wp;        // (q0,q0,q1,q1)
                float4 wB = *(const float4*)(wp + 4);  // (q2,q2,q3,q3)
                float4 h4 = *(const float4*)hp;        // (t0,t1,t2,t3)
                ull w0 = *(const ull*)&wA.x, w1 = *(const ull*)&wA.z;
                ull w2 = *(const ull*)&wB.x, w3 = *(const ull*)&wB.z;
                ull h01 = *(const ull*)&h4.x, h23 = *(const ull*)&h4.z;
                a00 = fma2_(w0, h01, a00);  a01 = fma2_(w0, h23, a01);
                a10 = fma2_(w1, h01, a10);  a11 = fma2_(w1, h23, a11);
                a20 = fma2_(w2, h01, a20);  a21 = fma2_(w2, h23, a21);
                a30 = fma2_(w3, h01, a30);  a31 = fma2_(w3, h23, a31);
                wp += 32; hp += 32;
            }
            // partials: one float4 (q0..q3) per t column
            {
                float4* dst = (float4*)&sgp[warp][g][4 * tq][0];
                dst[0] = make_float4(lo_(a00), lo_(a10), lo_(a20), lo_(a30));
                dst[1] = make_float4(hi_(a00), hi_(a10), hi_(a20), hi_(a30));
                dst[2] = make_float4(lo_(a01), lo_(a11), lo_(a21), lo_(a31));
                dst[3] = make_float4(hi_(a01), hi_(a11), hi_(a21), hi_(a31));
            }
            __syncthreads();

            // pointwise LSTM update over valid t range
            int v0 = (tb > s) ? tb : s;
            int vend = (tb + 32 < TT) ? tb + 32 : TT;
            int cnt = vend - v0;
            if (tid < 4 * cnt) {
                int tt = tid >> 2, q = tid & 3;
                int t = v0 + tt;
                int tc = t - tb;
                int u = t - s;
                int jb = k0 + q;
                float gi = g_gxb[u][jb];
                float gf = g_gxb[u][HH + jb];
                float gg = g_gxb[u][2 * HH + jb];
                float go = g_gxb[u][3 * HH + jb];
#pragma unroll
                for (int kq = 0; kq < 8; kq++) {
                    gi += sgp[kq][0][tc][q];
                    gf += sgp[kq][1][tc][q];
                    gg += sgp[kq][2][tc][q];
                    go += sgp[kq][3][tc][q];
                }
                float c  = scb[t][q];
                float cn = sigmoidf_(gf) * c + sigmoidf_(gi) * tanhf(gg);
                float hn = sigmoidf_(go) * tanhf(cn);
                scb[t][q] = cn;
                g_hbT[p2][jb][t] = hn;
                if (t == s) g_hb_final[t][jb] = hn;
            }
        }
        __syncthreads();

        // ======== grid barrier (release/acquire) ========
        if (tid == 0) {
            unsigned a;
            asm volatile("atom.acq_rel.gpu.add.u32 %0, [%1], %2;"
                         : "=r"(a) : "l"(&g_cnt), "r"(1u) : "memory");
            if (a == NB - 1) {
                asm volatile("st.relaxed.gpu.u32 [%0], %1;"
                             :: "l"(&g_cnt), "r"(0u) : "memory");
                asm volatile("st.release.gpu.u32 [%0], %1;"
                             :: "l"(&g_gen), "r"((unsigned)(s + 1)) : "memory");
            } else {
                unsigned gg;
                do {
                    asm volatile("ld.acquire.gpu.u32 %0, [%1];"
                                 : "=r"(gg) : "l"(&g_gen) : "memory");
                } while (gg < (unsigned)(s + 1));
            }
        }
        __syncthreads();
    }
}

// ---------------- final FC: logits = [hf|hb] @ fc_w^T + fc_b ----------------
// ONE t-block (128 rows) x 250 v-blocks of 128 -> fc_w streamed from DRAM ONCE.
// Smem k-major; A pre-duplicated (As2[k][2t],[2t+1]) so a-operands load as
// packed f32x2 pairs with no MOVs; acc packed over adjacent v pairs.
// Thread: ty=tid>>4 -> 8 t rows, tx=tid&15 -> 8 adjacent v cols.
#define FCK 32
#define FAP 260    // As2 row stride (2*128 + 4)
#define FBP 132    // Bs row stride (128 + 4)
__global__ void __launch_bounds__(256, 2)
fc_kernel(const float* __restrict__ fcw,
          const float* __restrict__ fcb,
          float* __restrict__ out) {
    extern __shared__ float fsm[];
    float* As2 = fsm;                // [FCK][FAP]
    float* Bs  = fsm + FCK * FAP;    // [FCK][FBP]
    int tid = threadIdx.x;  // 256
    int ty = tid >> 4;      // 0..15 -> t rows ty*8..+7
    int tx = tid & 15;      // 0..15 -> v cols tx*8..+7 (adjacent)
    int vbase = blockIdx.x * 128;

    ull acc2[8][4];
#pragma unroll
    for (int j = 0; j < 8; j++)
#pragma unroll
        for (int c = 0; c < 4; c++) acc2[j][c] = 0ull;

    for (int kc = 0; kc < KH2; kc += FCK) {
        // stage A (dup'd): thread covers (t = tid>>1, k-half = tid&1)
        {
            int t = tid >> 1, half = tid & 1;
            int kbase = kc + 16 * half;
            float4 a[4];
            if (t < TT) {
                const float* src = (kbase < HH) ? &g_hf_all[t][kbase]
                                                : &g_hb_final[t][kbase - HH];
#pragma unroll
                for (int j2 = 0; j2 < 4; j2++) a[j2] = ((const float4*)src)[j2];
            } else {
#pragma unroll
                for (int j2 = 0; j2 < 4; j2++)
                    a[j2] = make_float4(0.f, 0.f, 0.f, 0.f);
            }
#pragma unroll
            for (int j2 = 0; j2 < 4; j2++) {
                int kk = 16 * half + 4 * j2;
                *(float2*)&As2[(kk + 0) * FAP + 2 * t] = make_float2(a[j2].x, a[j2].x);
                *(float2*)&As2[(kk + 1) * FAP + 2 * t] = make_float2(a[j2].y, a[j2].y);
                *(float2*)&As2[(kk + 2) * FAP + 2 * t] = make_float2(a[j2].z, a[j2].z);
                *(float2*)&As2[(kk + 3) * FAP + 2 * t] = make_float2(a[j2].w, a[j2].w);
            }
        }
        // stage B: thread covers (v = tid>>1, k-half = tid&1)
        {
            int vv = tid >> 1, half = tid & 1;
            const float* src = fcw + (long)(vbase + vv) * KH2 + kc + 16 * half;
#pragma unroll
            for (int j2 = 0; j2 < 4; j2++) {
                float4 b = ((const float4*)src)[j2];
                int kk = 16 * half + 4 * j2;
                Bs[(kk + 0) * FBP + vv] = b.x;
                Bs[(kk + 1) * FBP + vv] = b.y;
                Bs[(kk + 2) * FBP + vv] = b.z;
                Bs[(kk + 3) * FBP + vv] = b.w;
            }
        }
        __syncthreads();

#pragma unroll 8
        for (int k = 0; k < FCK; k++) {
            const float* ap = As2 + k * FAP + 16 * ty;
            const float* bp = Bs + k * FBP + 8 * tx;
            float4 b0 = *(const float4*)bp;        // v0..v3
            float4 b1 = *(const float4*)(bp + 4);  // v4..v7
            ull bv[4];
            bv[0] = *(const ull*)&b0.x;  bv[1] = *(const ull*)&b0.z;
            bv[2] = *(const ull*)&b1.x;  bv[3] = *(const ull*)&b1.z;
#pragma unroll
            for (int jj = 0; jj < 4; jj++) {
                float4 av = *(const float4*)(ap + 4 * jj);   // (t,t, t+1,t+1)
                ull aL = *(const ull*)&av.x;
                ull aH = *(const ull*)&av.z;
#pragma unroll
                for (int c = 0; c < 4; c++) {
                    acc2[2 * jj][c]     = fma2_(aL, bv[c], acc2[2 * jj][c]);
                    acc2[2 * jj + 1][c] = fma2_(aH, bv[c], acc2[2 * jj + 1][c]);
                }
            }
        }
        __syncthreads();
    }

#pragma unroll
    for (int j = 0; j < 8; j++) {
        int t = ty * 8 + j;
        if (t >= TT) continue;
#pragma unroll
        for (int c = 0; c < 4; c++) {
            int v = vbase + 8 * tx + 2 * c;
            float2 r = make_float2(lo_(acc2[j][c]) + fcb[v],
                                   hi_(acc2[j][c]) + fcb[v + 1]);
            *(float2*)&out[(long)t * VV + v] = r;
        }
    }
}

// ---------------- launch ----------------
extern "C" void kernel_launch(void* const* d_in, const int* in_sizes, int n_in,
                              void* d_out, int out_size) {
    const int*   x      = (const int*)d_in[0];
    const float* emb    = (const float*)d_in[1];
    const float* W_ih_f = (const float*)d_in[2];
    const float* W_hh_f = (const float*)d_in[3];
    const float* b_ih_f = (const float*)d_in[4];
    const float* b_hh_f = (const float*)d_in[5];
    const float* W_ih_b = (const float*)d_in[6];
    const float* W_hh_b = (const float*)d_in[7];
    const float* b_ih_b = (const float*)d_in[8];
    const float* b_hh_b = (const float*)d_in[9];
    const float* fc_w   = (const float*)d_in[10];
    const float* fc_b   = (const float*)d_in[11];
    float* out = (float*)d_out;

    const int scanBytes = (512 * 32 + 2 * 512 * 32) * (int)sizeof(float); // 192KB
    cudaFuncSetAttribute(scan_kernel,
                         cudaFuncAttributeMaxDynamicSharedMemorySize, scanBytes);
    const int fcBytes = (FCK * FAP + FCK * FBP) * (int)sizeof(float);    // ~50KB
    cudaFuncSetAttribute(fc_kernel,
                         cudaFuncAttributeMaxDynamicSharedMemorySize, fcBytes);

    init_kernel<<<128, 256>>>();
    input_gemm_kernel<<<256, 128>>>(x, emb, W_ih_f, b_ih_f, b_hh_f,
                                    W_ih_b, b_ih_b, b_hh_b);
    scan_kernel<<<NB, NT, scanBytes>>>(W_hh_f, W_hh_b);
    fc_kernel<<<VV / 128, 256, fcBytes>>>(fc_w, fc_b, out);
}